// round 11
// baseline (speedup 1.0000x reference)
#include <cuda_runtime.h>
#include <cuda_fp16.h>
#include <cstdint>

#define B_    1024
#define T_    128
#define H_    512
#define RNNIN 128
#define LENV  1500
#define IPDV  256
#define EB    64
#define LAB   100

#define LDA  132
#define SMEM_BYTES (32768 + 32*LDA*4)   // sH 2 groups x 16KB + sAcc

__device__ float  g_Wc[H_ * RNNIN];
__device__ float  g_c[H_];
__device__ float  g_Alen[LENV * H_];
__device__ float  g_Aipd[IPDV * H_];
__device__ __half g_W16[H_ * H_];                          // h2h_w [n][k] fp16
__device__ __align__(256) __half g_h16[2][4][1024][128];   // [buf][kchunk][row][128h] swizzled
__device__ float  g_hlast[B_ * H_];

// ---------------- kernel A ----------------
__global__ void k_prep(const float* __restrict__ fc1_w, const float* __restrict__ fc1_b,
                       const float* __restrict__ x2h_w, const float* __restrict__ x2h_b,
                       const float* __restrict__ h2h_b) {
    __shared__ float s[RNNIN];
    int n = blockIdx.x, f = threadIdx.x;
    s[f] = x2h_w[n * RNNIN + f];
    __syncthreads();
    float acc = 0.f;
#pragma unroll 4
    for (int j = 0; j < RNNIN; ++j) acc += s[j] * fc1_w[j * 128 + f];
    g_Wc[n * RNNIN + f] = acc;
    if (f == 0) {
        float cb = x2h_b[n] + h2h_b[n];
        for (int j = 0; j < RNNIN; ++j) cb += s[j] * fc1_b[j];
        g_c[n] = cb;
    }
}

// ---------------- kernel B ----------------
#define RPB 16
__global__ void k_tables(const float* __restrict__ len_emb, const float* __restrict__ ipd_emb) {
    __shared__ float se[RPB][EB];
    int bid = blockIdx.x;
    const int lenBlocks = (LENV + RPB - 1) / RPB;
    bool isLen = bid < lenBlocks;
    int rbase, nrows, koff;
    const float* emb;
    float* dst;
    if (isLen) { rbase = bid * RPB;               nrows = LENV; koff = 0;  emb = len_emb; dst = g_Alen; }
    else       { rbase = (bid - lenBlocks) * RPB; nrows = IPDV; koff = EB; emb = ipd_emb; dst = g_Aipd; }
    for (int i = threadIdx.x; i < RPB * EB; i += blockDim.x) {
        int r = i / EB, k = i % EB;
        se[r][k] = (rbase + r < nrows) ? emb[(size_t)(rbase + r) * EB + k] : 0.f;
    }
    __syncthreads();
    int f = threadIdx.x;
    for (int q = 0; q < 4; ++q) {
        int n = q * 128 + f;
        float acc[RPB];
        float c0 = isLen ? g_c[n] : 0.f;
#pragma unroll
        for (int r = 0; r < RPB; ++r) acc[r] = c0;
        const float* wr = g_Wc + n * RNNIN + koff;
        for (int k = 0; k < EB; ++k) {
            float w = wr[k];
#pragma unroll
            for (int r = 0; r < RPB; ++r) acc[r] += w * se[r][k];
        }
        for (int r = 0; r < RPB; ++r)
            if (rbase + r < nrows) dst[(size_t)(rbase + r) * H_ + n] = acc[r];
    }
}

// ---------------- kernel C ----------------
__global__ void k_w16(const float* __restrict__ h2h_w) {
    int i = blockIdx.x * 256 + threadIdx.x;
    g_W16[i] = __float2half(h2h_w[i]);
}

// ---------------- helpers ----------------
__device__ __forceinline__ unsigned smem_u32(const void* p) {
    unsigned a;
    asm("{ .reg .u64 t; cvta.to.shared.u64 t, %1; cvt.u32.u64 %0, t; }" : "=r"(a) : "l"(p));
    return a;
}
__device__ __forceinline__ uint32_t h2_u32(__half2 h) {
    union { __half2 h; uint32_t u; } cv;
    cv.h = h;
    return cv.u;
}
#define MBAR_INIT(a, c) asm volatile("mbarrier.init.shared.b64 [%0], %1;" :: "r"(a), "r"(c) : "memory")
#define MBAR_TX(a, b)   asm volatile("mbarrier.arrive.expect_tx.shared.b64 _, [%0], %1;" :: "r"(a), "r"(b) : "memory")
#define MBAR_WAIT(a, p) do { \
    asm volatile("{\n\t.reg .pred P;\n\tWL_%=:\n\t" \
        "mbarrier.try_wait.parity.acquire.cta.shared::cta.b64 P, [%0], %1, 0x989680;\n\t" \
        "@P bra.uni WD_%=;\n\tbra.uni WL_%=;\n\tWD_%=:\n\t}" :: "r"(a), "r"(p) : "memory"); } while (0)
#define BULK_G2S(d, s, n, m) \
    asm volatile("cp.async.bulk.shared::cta.global.mbarrier::complete_tx::bytes [%0], [%1], %2, [%3];" \
        :: "r"(d), "l"(s), "r"(n), "r"(m) : "memory")
#define CARRIVE() asm volatile("barrier.cluster.arrive.aligned;" ::: "memory")
#define CWAIT()   asm volatile("barrier.cluster.wait.aligned;"   ::: "memory")
#define FENCEA()  asm volatile("fence.proxy.async;" ::: "memory")

// ---------------- kernel D: recurrence, two-group pipeline ----------------
__global__ void __cluster_dims__(4, 1, 1) __launch_bounds__(256, 1)
k_rnn(const int* __restrict__ x) {
    extern __shared__ __half smem[];
    __shared__ __align__(8) unsigned long long mbar[8];   // [group][chunk]
    float* sAcc = (float*)(smem + 16384);                 // [32][LDA]
    const unsigned sHu = smem_u32(smem);                  // [2 grp][4 chunk][16 row][128h]
    const unsigned mbu = smem_u32(mbar);

    const int rank = blockIdx.x & 3, cid = blockIdx.x >> 2;
    const int batch0 = cid * 32, n0 = rank * 128, tid = threadIdx.x;
    const int w = tid >> 5, lane = tid & 31;
    const int gid = lane >> 2, tig = lane & 3;
    const int nw = n0 + w * 16;
    const int r15 = lane & 15, g15 = lane >> 4;

    if (tid == 0) {
#pragma unroll
        for (int c = 0; c < 8; ++c) MBAR_INIT(mbu + 8 * c, 1);
    }
    __syncthreads();

    // persistent W fragments: 32 kk x 2 n8 x 2 regs
    uint32_t bw[32][2][2];
#pragma unroll
    for (int kk = 0; kk < 32; ++kk)
#pragma unroll
        for (int j = 0; j < 2; ++j) {
            const __half* wp = g_W16 + (size_t)(nw + j * 8 + gid) * H_ + kk * 16 + tig * 2;
            bw[kk][j][0] = *(const uint32_t*)wp;
            bw[kk][j][1] = *(const uint32_t*)(wp + 8);
        }

    // epilogue mapping: 16 rows x 16 unit-cols (8 cols each)
    const int er = tid >> 4, uc = tid & 15;
    const int eb0 = batch0 + er, eb1 = batch0 + 16 + er;
    const int* xq0 = x + (size_t)eb0 * T_ * 2;
    const int* xq1 = x + (size_t)eb1 * T_ * 2;
    const unsigned swz = ((unsigned)uc ^ (unsigned)er) << 4;
    char* const hb0 = (char*)g_h16 + ((size_t)rank * 1024 + eb0) * 256 + swz;
    char* const hb1 = (char*)g_h16 + ((size_t)rank * 1024 + eb1) * 256 + swz;
    const int ncol = n0 + uc * 8;
    float4* const dl0 = (float4*)(g_hlast + (size_t)eb0 * H_ + ncol);
    float4* const dl1 = (float4*)(g_hlast + (size_t)eb1 * H_ + ncol);

    float4 tl[2], ti[2];

    // ---------------- prologue: t = 0 for both groups ----------------
    {
        int a0 = xq0[0], a1 = xq0[1], b0 = xq1[0], b1 = xq1[1];
        const float4* pl = (const float4*)(g_Alen + (size_t)a0 * H_ + ncol);
        const float4* pi = (const float4*)(g_Aipd + (size_t)a1 * H_ + ncol);
        uint32_t hv[4];
#pragma unroll
        for (int j = 0; j < 2; ++j) {
            float4 l = pl[j], i4 = pi[j];
            hv[2 * j]     = h2_u32(__floats2half2_rn(tanhf(l.x + i4.x), tanhf(l.y + i4.y)));
            hv[2 * j + 1] = h2_u32(__floats2half2_rn(tanhf(l.z + i4.z), tanhf(l.w + i4.w)));
        }
        *(uint4*)hb0 = ((uint4*)hv)[0];
        pl = (const float4*)(g_Alen + (size_t)b0 * H_ + ncol);
        pi = (const float4*)(g_Aipd + (size_t)b1 * H_ + ncol);
#pragma unroll
        for (int j = 0; j < 2; ++j) {
            float4 l = pl[j], i4 = pi[j];
            hv[2 * j]     = h2_u32(__floats2half2_rn(tanhf(l.x + i4.x), tanhf(l.y + i4.y)));
            hv[2 * j + 1] = h2_u32(__floats2half2_rn(tanhf(l.z + i4.z), tanhf(l.w + i4.w)));
        }
        *(uint4*)hb1 = ((uint4*)hv)[0];
        FENCEA();
        CARRIVE(); CWAIT();                 // phase 0: h0 stored everywhere
        if (tid == 0) {                     // issue G0 bulks (h0, buf 0)
#pragma unroll
            for (int c = 0; c < 4; ++c) {
                MBAR_TX(mbu + 8 * c, 4096);
                BULK_G2S(sHu + c * 4096,
                         (const char*)g_h16 + (size_t)c * 262144 + (size_t)batch0 * 256,
                         4096, mbu + 8 * c);
            }
        }
        CARRIVE();                          // phase 1 (matched by wait in t=1)
    }

    // ---------------- main loop ----------------
    for (int t = 1; t < T_; ++t) {
        const int p = (t - 1) & 1;
        const size_t rbuf = (size_t)p * 1048576;          // read buf (h_{t-1})
        const size_t wbuf = (size_t)(t & 1) * 1048576;    // write buf (h_t)
        const bool last = (t == T_ - 1);

        // prefetch G0 tables
        {
            int a0 = xq0[2 * t], a1 = xq0[2 * t + 1];
            const float4* pl = (const float4*)(g_Alen + (size_t)a0 * H_ + ncol);
            const float4* pi = (const float4*)(g_Aipd + (size_t)a1 * H_ + ncol);
            tl[0] = pl[0]; tl[1] = pl[1]; ti[0] = pi[0]; ti[1] = pi[1];
        }

        // ======== GEMM G0 ========
        float ac[2][4];
#pragma unroll
        for (int j = 0; j < 2; ++j)
#pragma unroll
            for (int q = 0; q < 4; ++q) ac[j][q] = 0.f;
#pragma unroll
        for (int c = 0; c < 4; ++c) {
            MBAR_WAIT(mbu + 8 * c, p);
#pragma unroll
            for (int kc = 0; kc < 8; ++kc) {
                unsigned ad = sHu + c * 4096 + r15 * 256
                            + (((unsigned)(2 * kc + g15) ^ (unsigned)r15) << 4);
                uint32_t a0, a1, a2, a3;
                asm volatile("ldmatrix.sync.aligned.m8n8.x4.shared.b16 {%0,%1,%2,%3}, [%4];"
                             : "=r"(a0), "=r"(a1), "=r"(a2), "=r"(a3) : "r"(ad));
                const int kk = c * 8 + kc;
#pragma unroll
                for (int j = 0; j < 2; ++j)
                    asm volatile(
                        "mma.sync.aligned.m16n8k16.row.col.f32.f16.f16.f32 "
                        "{%0,%1,%2,%3},{%4,%5,%6,%7},{%8,%9},{%0,%1,%2,%3};"
                        : "+f"(ac[j][0]), "+f"(ac[j][1]), "+f"(ac[j][2]), "+f"(ac[j][3])
                        : "r"(a0), "r"(a1), "r"(a2), "r"(a3),
                          "r"(bw[kk][j][0]), "r"(bw[kk][j][1]));
            }
        }
#pragma unroll
        for (int j = 0; j < 2; ++j) {
            int n = w * 16 + j * 8 + tig * 2;
            float* p0 = sAcc + gid * LDA + n;
            float* p1 = sAcc + (gid + 8) * LDA + n;
            p0[0] = ac[j][0]; p0[1] = ac[j][1];
            p1[0] = ac[j][2]; p1[1] = ac[j][3];
        }
        __syncthreads();

        // wait "G1 h_{t-1} stored" (arrived end of prev iter / prologue), issue G1 bulks
        CWAIT();
        if (tid == 0) {
#pragma unroll
            for (int c = 0; c < 4; ++c) {
                MBAR_TX(mbu + 32 + 8 * c, 4096);
                BULK_G2S(sHu + 16384 + c * 4096,
                         (const char*)g_h16 + rbuf + (size_t)c * 262144 + (size_t)(batch0 + 16) * 256,
                         4096, mbu + 32 + 8 * c);
            }
        }

        // ======== epilogue G0 ========
        {
            const float4* pq = (const float4*)(sAcc + er * LDA + uc * 8);
            float4 q0 = pq[0], q1 = pq[1];
            float o0 = tanhf(q0.x + tl[0].x + ti[0].x);
            float o1 = tanhf(q0.y + tl[0].y + ti[0].y);
            float o2 = tanhf(q0.z + tl[0].z + ti[0].z);
            float o3 = tanhf(q0.w + tl[0].w + ti[0].w);
            float o4 = tanhf(q1.x + tl[1].x + ti[1].x);
            float o5 = tanhf(q1.y + tl[1].y + ti[1].y);
            float o6 = tanhf(q1.z + tl[1].z + ti[1].z);
            float o7 = tanhf(q1.w + tl[1].w + ti[1].w);
            if (!last) {
                uint32_t hv[4];
                hv[0] = h2_u32(__floats2half2_rn(o0, o1));
                hv[1] = h2_u32(__floats2half2_rn(o2, o3));
                hv[2] = h2_u32(__floats2half2_rn(o4, o5));
                hv[3] = h2_u32(__floats2half2_rn(o6, o7));
                *(uint4*)(hb0 + wbuf) = ((uint4*)hv)[0];
                FENCEA();
            } else {
                dl0[0] = make_float4(o0, o1, o2, o3);
                dl0[1] = make_float4(o4, o5, o6, o7);
            }
        }
        if (!last) CARRIVE();     // "G0 h_t stored"

        // prefetch G1 tables
        {
            int b0 = xq1[2 * t], b1 = xq1[2 * t + 1];
            const float4* pl = (const float4*)(g_Alen + (size_t)b0 * H_ + ncol);
            const float4* pi = (const float4*)(g_Aipd + (size_t)b1 * H_ + ncol);
            tl[0] = pl[0]; tl[1] = pl[1]; ti[0] = pi[0]; ti[1] = pi[1];
        }

        // ======== GEMM G1 ========
#pragma unroll
        for (int j = 0; j < 2; ++j)
#pragma unroll
            for (int q = 0; q < 4; ++q) ac[j][q] = 0.f;
#pragma unroll
        for (int c = 0; c < 4; ++c) {
            MBAR_WAIT(mbu + 32 + 8 * c, p);
#pragma unroll
            for (int kc = 0; kc < 8; ++kc) {
                unsigned ad = sHu + 16384 + c * 4096 + r15 * 256
                            + (((unsigned)(2 * kc + g15) ^ (unsigned)r15) << 4);
                uint32_t a0, a1, a2, a3;
                asm volatile("ldmatrix.sync.aligned.m8n8.x4.shared.b16 {%0,%1,%2,%3}, [%4];"
                             : "=r"(a0), "=r"(a1), "=r"(a2), "=r"(a3) : "r"(ad));
                const int kk = c * 8 + kc;
#pragma unroll
                for (int j = 0; j < 2; ++j)
                    asm volatile(
                        "mma.sync.aligned.m16n8k16.row.col.f32.f16.f16.f32 "
                        "{%0,%1,%2,%3},{%4,%5,%6,%7},{%8,%9},{%0,%1,%2,%3};"
                        : "+f"(ac[j][0]), "+f"(ac[j][1]), "+f"(ac[j][2]), "+f"(ac[j][3])
                        : "r"(a0), "r"(a1), "r"(a2), "r"(a3),
                          "r"(bw[kk][j][0]), "r"(bw[kk][j][1]));
            }
        }
#pragma unroll
        for (int j = 0; j < 2; ++j) {
            int n = w * 16 + j * 8 + tig * 2;
            float* p0 = sAcc + (16 + gid) * LDA + n;
            float* p1 = sAcc + (16 + gid + 8) * LDA + n;
            p0[0] = ac[j][0]; p0[1] = ac[j][1];
            p1[0] = ac[j][2]; p1[1] = ac[j][3];
        }
        __syncthreads();

        // wait "G0 h_t stored", issue G0 bulks for t+1
        if (!last) {
            CWAIT();
            if (tid == 0) {
#pragma unroll
                for (int c = 0; c < 4; ++c) {
                    MBAR_TX(mbu + 8 * c, 4096);
                    BULK_G2S(sHu + c * 4096,
                             (const char*)g_h16 + wbuf + (size_t)c * 262144 + (size_t)batch0 * 256,
                             4096, mbu + 8 * c);
                }
            }
        }

        // ======== epilogue G1 ========
        {
            const float4* pq = (const float4*)(sAcc + (16 + er) * LDA + uc * 8);
            float4 q0 = pq[0], q1 = pq[1];
            float o0 = tanhf(q0.x + tl[0].x + ti[0].x);
            float o1 = tanhf(q0.y + tl[0].y + ti[0].y);
            float o2 = tanhf(q0.z + tl[0].z + ti[0].z);
            float o3 = tanhf(q0.w + tl[0].w + ti[0].w);
            float o4 = tanhf(q1.x + tl[1].x + ti[1].x);
            float o5 = tanhf(q1.y + tl[1].y + ti[1].y);
            float o6 = tanhf(q1.z + tl[1].z + ti[1].z);
            float o7 = tanhf(q1.w + tl[1].w + ti[1].w);
            if (!last) {
                uint32_t hv[4];
                hv[0] = h2_u32(__floats2half2_rn(o0, o1));
                hv[1] = h2_u32(__floats2half2_rn(o2, o3));
                hv[2] = h2_u32(__floats2half2_rn(o4, o5));
                hv[3] = h2_u32(__floats2half2_rn(o6, o7));
                *(uint4*)(hb1 + wbuf) = ((uint4*)hv)[0];
                FENCEA();
                CARRIVE();        // "G1 h_t stored" (matched by CWAIT in next iter)
            } else {
                dl1[0] = make_float4(o0, o1, o2, o3);
                dl1[1] = make_float4(o4, o5, o6, o7);
            }
        }
    }
}

// ---------------- kernel E: fc2 ----------------
__global__ void k_fc2(const float* __restrict__ fc2_w, const float* __restrict__ fc2_b,
                      float* __restrict__ out) {
    __shared__ float sh[16][H_];
    int batch0 = blockIdx.x * 16;
    for (int i = threadIdx.x; i < 16 * H_; i += 256) {
        int r = i >> 9, k = i & (H_ - 1);
        sh[r][k] = g_hlast[(size_t)(batch0 + r) * H_ + k];
    }
    __syncthreads();
    int tid = threadIdx.x;
    if (tid < 200) {
        int l = tid % 100, bh = tid / 100;
        float acc[8];
        float bias = fc2_b[l];
#pragma unroll
        for (int i = 0; i < 8; ++i) acc[i] = bias;
        const float4* wr = (const float4*)(fc2_w + (size_t)l * H_);
        for (int k4 = 0; k4 < H_ / 4; ++k4) {
            float4 wv = wr[k4];
#pragma unroll
            for (int i = 0; i < 8; ++i) {
                float4 h = *(const float4*)(&sh[bh * 8 + i][k4 * 4]);
                acc[i] += wv.x * h.x + wv.y * h.y + wv.z * h.z + wv.w * h.w;
            }
        }
        for (int i = 0; i < 8; ++i)
            out[(size_t)(batch0 + bh * 8 + i) * LAB + l] = acc[i];
    }
}

// ---------------- launch ----------------
extern "C" void kernel_launch(void* const* d_in, const int* in_sizes, int n_in,
                              void* d_out, int out_size) {
    const int* x         = (const int*)d_in[0];
    const float* len_emb = (const float*)d_in[1];
    const float* ipd_emb = (const float*)d_in[2];
    const float* fc1_w   = (const float*)d_in[3];
    const float* fc1_b   = (const float*)d_in[4];
    const float* x2h_w   = (const float*)d_in[5];
    const float* x2h_b   = (const float*)d_in[6];
    const float* h2h_w   = (const float*)d_in[7];
    const float* h2h_b   = (const float*)d_in[8];
    const float* fc2_w   = (const float*)d_in[9];
    const float* fc2_b   = (const float*)d_in[10];
    float* out = (float*)d_out;

    cudaFuncSetAttribute(k_rnn, cudaFuncAttributeMaxDynamicSharedMemorySize, SMEM_BYTES);

    k_prep  <<<512, 128>>>(fc1_w, fc1_b, x2h_w, x2h_b, h2h_b);
    k_tables<<<(LENV + RPB - 1) / RPB + IPDV / RPB, 128>>>(len_emb, ipd_emb);
    k_w16   <<<H_ * H_ / 256, 256>>>(h2h_w);
    k_rnn   <<<128, 256, SMEM_BYTES>>>(x);
    k_fc2   <<<B_ / 16, 256>>>(fc2_w, fc2_b, out);
}

// round 12
// speedup vs baseline: 1.0379x; 1.0379x over previous
#include <cuda_runtime.h>
#include <cuda_fp16.h>
#include <cstdint>

#define B_    1024
#define T_    128
#define H_    512
#define RNNIN 128
#define LENV  1500
#define IPDV  256
#define EB    64
#define LAB   100

#define LDA  132
#define SMEM_BYTES (65536 + 32*LDA*4)   // sH 2 bufs x 4 chunks x 8KB + sAcc

__device__ float  g_Wc[H_ * RNNIN];
__device__ float  g_c[H_];
__device__ float  g_Alen[LENV * H_];
__device__ float  g_Aipd[IPDV * H_];
__device__ __half g_W16[H_ * H_];                          // h2h_w [n][k] fp16
__device__ __align__(256) __half g_h16[2][4][1024][128];   // [buf][kchunk][row][128h] swizzled
__device__ float  g_hlast[B_ * H_];

// ---------------- kernel A ----------------
__global__ void k_prep(const float* __restrict__ fc1_w, const float* __restrict__ fc1_b,
                       const float* __restrict__ x2h_w, const float* __restrict__ x2h_b,
                       const float* __restrict__ h2h_b) {
    __shared__ float s[RNNIN];
    int n = blockIdx.x, f = threadIdx.x;
    s[f] = x2h_w[n * RNNIN + f];
    __syncthreads();
    float acc = 0.f;
#pragma unroll 4
    for (int j = 0; j < RNNIN; ++j) acc += s[j] * fc1_w[j * 128 + f];
    g_Wc[n * RNNIN + f] = acc;
    if (f == 0) {
        float cb = x2h_b[n] + h2h_b[n];
        for (int j = 0; j < RNNIN; ++j) cb += s[j] * fc1_b[j];
        g_c[n] = cb;
    }
}

// ---------------- kernel B ----------------
#define RPB 16
__global__ void k_tables(const float* __restrict__ len_emb, const float* __restrict__ ipd_emb) {
    __shared__ float se[RPB][EB];
    int bid = blockIdx.x;
    const int lenBlocks = (LENV + RPB - 1) / RPB;
    bool isLen = bid < lenBlocks;
    int rbase, nrows, koff;
    const float* emb;
    float* dst;
    if (isLen) { rbase = bid * RPB;               nrows = LENV; koff = 0;  emb = len_emb; dst = g_Alen; }
    else       { rbase = (bid - lenBlocks) * RPB; nrows = IPDV; koff = EB; emb = ipd_emb; dst = g_Aipd; }
    for (int i = threadIdx.x; i < RPB * EB; i += blockDim.x) {
        int r = i / EB, k = i % EB;
        se[r][k] = (rbase + r < nrows) ? emb[(size_t)(rbase + r) * EB + k] : 0.f;
    }
    __syncthreads();
    int f = threadIdx.x;
    for (int q = 0; q < 4; ++q) {
        int n = q * 128 + f;
        float acc[RPB];
        float c0 = isLen ? g_c[n] : 0.f;
#pragma unroll
        for (int r = 0; r < RPB; ++r) acc[r] = c0;
        const float* wr = g_Wc + n * RNNIN + koff;
        for (int k = 0; k < EB; ++k) {
            float w = wr[k];
#pragma unroll
            for (int r = 0; r < RPB; ++r) acc[r] += w * se[r][k];
        }
        for (int r = 0; r < RPB; ++r)
            if (rbase + r < nrows) dst[(size_t)(rbase + r) * H_ + n] = acc[r];
    }
}

// ---------------- kernel C ----------------
__global__ void k_w16(const float* __restrict__ h2h_w) {
    int i = blockIdx.x * 256 + threadIdx.x;
    g_W16[i] = __float2half(h2h_w[i]);
}

// ---------------- helpers ----------------
__device__ __forceinline__ unsigned smem_u32(const void* p) {
    unsigned a;
    asm("{ .reg .u64 t; cvta.to.shared.u64 t, %1; cvt.u32.u64 %0, t; }" : "=r"(a) : "l"(p));
    return a;
}
__device__ __forceinline__ uint32_t h2_u32(__half2 h) {
    union { __half2 h; uint32_t u; } cv;
    cv.h = h;
    return cv.u;
}
#define MBAR_INIT(a, c) asm volatile("mbarrier.init.shared.b64 [%0], %1;" :: "r"(a), "r"(c) : "memory")
#define MBAR_TX(a, b)   asm volatile("mbarrier.arrive.expect_tx.shared.b64 _, [%0], %1;" :: "r"(a), "r"(b) : "memory")
#define MBAR_WAIT(a, p) do { \
    asm volatile("{\n\t.reg .pred P;\n\tWL_%=:\n\t" \
        "mbarrier.try_wait.parity.acquire.cta.shared::cta.b64 P, [%0], %1, 0x989680;\n\t" \
        "@P bra.uni WD_%=;\n\tbra.uni WL_%=;\n\tWD_%=:\n\t}" :: "r"(a), "r"(p) : "memory"); } while (0)
#define BULK_G2S(d, s, n, m) \
    asm volatile("cp.async.bulk.shared::cta.global.mbarrier::complete_tx::bytes [%0], [%1], %2, [%3];" \
        :: "r"(d), "l"(s), "r"(n), "r"(m) : "memory")
#define CARRIVE() asm volatile("barrier.cluster.arrive.aligned;" ::: "memory")
#define CWAIT()   asm volatile("barrier.cluster.wait.aligned;"   ::: "memory")
#define FENCEA()  asm volatile("fence.proxy.async;" ::: "memory")

// one k-chunk (cc) GEMM over kc in [k0,k1)
#define GEMM_CHUNK(cc, k0, k1) do { \
    _Pragma("unroll") \
    for (int kc = (k0); kc < (k1); ++kc) { \
        _Pragma("unroll") \
        for (int mt = 0; mt < 2; ++mt) { \
            unsigned ad = sHu + rsm + (unsigned)(cc) * 8192u + (unsigned)(mt * 16 + r15) * 256u \
                        + (((unsigned)(2 * kc + g15) ^ (unsigned)r15) << 4); \
            uint32_t a0, a1, a2, a3; \
            asm volatile("ldmatrix.sync.aligned.m8n8.x4.shared.b16 {%0,%1,%2,%3}, [%4];" \
                         : "=r"(a0), "=r"(a1), "=r"(a2), "=r"(a3) : "r"(ad)); \
            const int kk = (cc) * 8 + kc; \
            _Pragma("unroll") \
            for (int j = 0; j < 2; ++j) \
                asm volatile( \
                    "mma.sync.aligned.m16n8k16.row.col.f32.f16.f16.f32 " \
                    "{%0,%1,%2,%3},{%4,%5,%6,%7},{%8,%9},{%0,%1,%2,%3};" \
                    : "+f"(ac[mt][j][0]), "+f"(ac[mt][j][1]), \
                      "+f"(ac[mt][j][2]), "+f"(ac[mt][j][3]) \
                    : "r"(a0), "r"(a1), "r"(a2), "r"(a3), \
                      "r"(bw[kk][j][0]), "r"(bw[kk][j][1])); \
        } \
    } \
} while (0)

// ---------------- kernel D: recurrence ----------------
__global__ void __cluster_dims__(4, 1, 1) __launch_bounds__(256, 1)
k_rnn(const int* __restrict__ x) {
    extern __shared__ __half smem[];
    __shared__ __align__(8) unsigned long long mbar[4];
    char* sB = (char*)smem;                      // 2 bufs x 4 chunks x [32][128h] swizzled
    float* sAcc = (float*)(sB + 65536);          // [32][LDA]
    const unsigned sHu = smem_u32(sB);
    const unsigned mbu = smem_u32(mbar);

    const int rank = blockIdx.x & 3, cid = blockIdx.x >> 2;
    const int batch0 = cid * 32, n0 = rank * 128, tid = threadIdx.x;
    const int w = tid >> 5, lane = tid & 31;
    const int gid = lane >> 2, tig = lane & 3;
    const int nw = n0 + w * 16;
    const int r15 = lane & 15, g15 = lane >> 4;

    if (tid == 0) {
#pragma unroll
        for (int c = 0; c < 4; ++c) MBAR_INIT(mbu + 8 * c, 1);
    }
    __syncthreads();

    // persistent W fragments: 32 kk x 2 n8 x 2 regs
    uint32_t bw[32][2][2];
#pragma unroll
    for (int kk = 0; kk < 32; ++kk)
#pragma unroll
        for (int j = 0; j < 2; ++j) {
            const __half* wp = g_W16 + (size_t)(nw + j * 8 + gid) * H_ + kk * 16 + tig * 2;
            bw[kk][j][0] = *(const uint32_t*)wp;
            bw[kk][j][1] = *(const uint32_t*)(wp + 8);
        }

    // epilogue mapping: row er, 16 cols at nl
    const int er = tid >> 3, nl = (tid & 7) * 16;
    const int eb = batch0 + er;
    const int* xp = x + (size_t)eb * T_ * 2;
    const unsigned sswz = (unsigned)(er & 15);
    const int u0 = (tid & 7) * 2;
    // global h row base (chunk = rank); swizzled unit offsets
    char* const hg0 = (char*)g_h16 + ((size_t)rank * 1024 + eb) * 256 + (((unsigned)u0 ^ sswz) << 4);
    char* const hg1 = (char*)g_h16 + ((size_t)rank * 1024 + eb) * 256 + (((unsigned)(u0 + 1) ^ sswz) << 4);
    // local smem STS addresses for the same data (buffer 0 frame)
    char* const hs0 = sB + rank * 8192 + er * 256 + (((unsigned)u0 ^ sswz) << 4);
    char* const hs1 = sB + rank * 8192 + er * 256 + (((unsigned)(u0 + 1) ^ sswz) << 4);
    float4* const dlast = (float4*)(g_hlast + (size_t)eb * H_ + n0 + nl);

    // ---------------- t = 0 (epilogue-only, h0 = 0) ----------------
    float4 tl[4], ti[4];
    {
        int i0 = xp[0], i1 = xp[1];
        const float4* pa = (const float4*)(g_Alen + (size_t)i0 * H_ + n0 + nl);
        const float4* pb = (const float4*)(g_Aipd + (size_t)i1 * H_ + n0 + nl);
#pragma unroll
        for (int j = 0; j < 4; ++j) { tl[j] = pa[j]; ti[j] = pb[j]; }
        uint32_t hv[8];
#pragma unroll
        for (int j = 0; j < 4; ++j) {
            float4 o;
            o.x = tanhf(tl[j].x + ti[j].x);
            o.y = tanhf(tl[j].y + ti[j].y);
            o.z = tanhf(tl[j].z + ti[j].z);
            o.w = tanhf(tl[j].w + ti[j].w);
            hv[j * 2]     = h2_u32(__floats2half2_rn(o.x, o.y));
            hv[j * 2 + 1] = h2_u32(__floats2half2_rn(o.z, o.w));
        }
        *(uint4*)hs0 = ((uint4*)hv)[0];          // local chunk, buffer 0
        *(uint4*)hs1 = ((uint4*)hv)[1];
        *(uint4*)hg0 = ((uint4*)hv)[0];          // global for peers, buffer 0
        *(uint4*)hg1 = ((uint4*)hv)[1];
        // prefetch tables for t=1
        int j0 = xp[2], j1 = xp[3];
        const float4* qa = (const float4*)(g_Alen + (size_t)j0 * H_ + n0 + nl);
        const float4* qb = (const float4*)(g_Aipd + (size_t)j1 * H_ + n0 + nl);
#pragma unroll
        for (int j = 0; j < 4; ++j) { tl[j] = qa[j]; ti[j] = qb[j]; }
        FENCEA();
        CARRIVE();
    }
    __syncthreads();

    // ---------------- t = 1 .. 127 ----------------
    for (int t = 1; t < T_; ++t) {
        const int p = (t - 1) & 1;
        const unsigned rsm = (unsigned)p * 32768u;       // smem read buffer
        const size_t   rgb = (size_t)p * 1048576;        // global read buffer
        const bool last = (t == T_ - 1);

        float ac[2][2][4];
#pragma unroll
        for (int mt = 0; mt < 2; ++mt)
#pragma unroll
            for (int j = 0; j < 2; ++j)
#pragma unroll
                for (int q = 0; q < 4; ++q) ac[mt][j][q] = 0.f;

        // local chunk first half (covers cluster-barrier skew)
        GEMM_CHUNK(rank, 0, 4);
        CWAIT();
        if (tid == 0) {
#pragma unroll
            for (int i = 1; i < 4; ++i) {
                int c = (rank + i) & 3;
                MBAR_TX(mbu + 8 * c, 8192);
                BULK_G2S(sHu + rsm + c * 8192u,
                         (const char*)g_h16 + rgb + (size_t)c * 262144 + (size_t)batch0 * 256,
                         8192, mbu + 8 * c);
            }
        }
        // local chunk second half (covers part of L2 round trip)
        GEMM_CHUNK(rank, 4, 8);
        // remote chunks as they land
#pragma unroll
        for (int i = 1; i < 4; ++i) {
            int c = (rank + i) & 3;
            MBAR_WAIT(mbu + 8 * c, p);
            GEMM_CHUNK(c, 0, 8);
        }

        // stash acc to sAcc for row-coherent epilogue
#pragma unroll
        for (int mt = 0; mt < 2; ++mt)
#pragma unroll
            for (int j = 0; j < 2; ++j) {
                int n = w * 16 + j * 8 + tig * 2;
                float* p0 = sAcc + (mt * 16 + gid) * LDA + n;
                float* p1 = sAcc + (mt * 16 + gid + 8) * LDA + n;
                p0[0] = ac[mt][j][0]; p0[1] = ac[mt][j][1];
                p1[0] = ac[mt][j][2]; p1[1] = ac[mt][j][3];
            }
        __syncthreads();

        // epilogue: tanh(acc + A_len + A_ipd)
        const float4* pq = (const float4*)(sAcc + er * LDA + nl);
        uint32_t hv[8];
        float4 fres[4];
#pragma unroll
        for (int j = 0; j < 4; ++j) {
            float4 qa = pq[j];
            float4 o;
            o.x = tanhf(qa.x + tl[j].x + ti[j].x);
            o.y = tanhf(qa.y + tl[j].y + ti[j].y);
            o.z = tanhf(qa.z + tl[j].z + ti[j].z);
            o.w = tanhf(qa.w + tl[j].w + ti[j].w);
            fres[j] = o;
            hv[j * 2]     = h2_u32(__floats2half2_rn(o.x, o.y));
            hv[j * 2 + 1] = h2_u32(__floats2half2_rn(o.z, o.w));
        }
        if (!last) {
            const unsigned wsm = (unsigned)(t & 1) * 32768u;
            const size_t   wgb = (size_t)(t & 1) * 1048576;
            *(uint4*)(hs0 + wsm) = ((uint4*)hv)[0];   // local chunk for own next GEMM
            *(uint4*)(hs1 + wsm) = ((uint4*)hv)[1];
            *(uint4*)(hg0 + wgb) = ((uint4*)hv)[0];   // global for peers
            *(uint4*)(hg1 + wgb) = ((uint4*)hv)[1];
            // prefetch tables for t+1
            int j0 = xp[2 * (t + 1)], j1 = xp[2 * (t + 1) + 1];
            const float4* qa2 = (const float4*)(g_Alen + (size_t)j0 * H_ + n0 + nl);
            const float4* qb2 = (const float4*)(g_Aipd + (size_t)j1 * H_ + n0 + nl);
#pragma unroll
            for (int j = 0; j < 4; ++j) { tl[j] = qa2[j]; ti[j] = qb2[j]; }
            FENCEA();
            CARRIVE();                 // non-blocking; matched by CWAIT next step
            __syncthreads();           // STS visibility + sAcc WAR for next GEMM
        } else {
            dlast[0] = fres[0]; dlast[1] = fres[1];
            dlast[2] = fres[2]; dlast[3] = fres[3];
        }
    }
}

// ---------------- kernel E: fc2 ----------------
__global__ void k_fc2(const float* __restrict__ fc2_w, const float* __restrict__ fc2_b,
                      float* __restrict__ out) {
    __shared__ float sh[16][H_];
    int batch0 = blockIdx.x * 16;
    for (int i = threadIdx.x; i < 16 * H_; i += 256) {
        int r = i >> 9, k = i & (H_ - 1);
        sh[r][k] = g_hlast[(size_t)(batch0 + r) * H_ + k];
    }
    __syncthreads();
    int tid = threadIdx.x;
    if (tid < 200) {
        int l = tid % 100, bh = tid / 100;
        float acc[8];
        float bias = fc2_b[l];
#pragma unroll
        for (int i = 0; i < 8; ++i) acc[i] = bias;
        const float4* wr = (const float4*)(fc2_w + (size_t)l * H_);
        for (int k4 = 0; k4 < H_ / 4; ++k4) {
            float4 wv = wr[k4];
#pragma unroll
            for (int i = 0; i < 8; ++i) {
                float4 h = *(const float4*)(&sh[bh * 8 + i][k4 * 4]);
                acc[i] += wv.x * h.x + wv.y * h.y + wv.z * h.z + wv.w * h.w;
            }
        }
        for (int i = 0; i < 8; ++i)
            out[(size_t)(batch0 + bh * 8 + i) * LAB + l] = acc[i];
    }
}

// ---------------- launch ----------------
extern "C" void kernel_launch(void* const* d_in, const int* in_sizes, int n_in,
                              void* d_out, int out_size) {
    const int* x         = (const int*)d_in[0];
    const float* len_emb = (const float*)d_in[1];
    const float* ipd_emb = (const float*)d_in[2];
    const float* fc1_w   = (const float*)d_in[3];
    const float* fc1_b   = (const float*)d_in[4];
    const float* x2h_w   = (const float*)d_in[5];
    const float* x2h_b   = (const float*)d_in[6];
    const float* h2h_w   = (const float*)d_in[7];
    const float* h2h_b   = (const float*)d_in[8];
    const float* fc2_w   = (const float*)d_in[9];
    const float* fc2_b   = (const float*)d_in[10];
    float* out = (float*)d_out;

    cudaFuncSetAttribute(k_rnn, cudaFuncAttributeMaxDynamicSharedMemorySize, SMEM_BYTES);

    k_prep  <<<512, 128>>>(fc1_w, fc1_b, x2h_w, x2h_b, h2h_b);
    k_tables<<<(LENV + RPB - 1) / RPB + IPDV / RPB, 128>>>(len_emb, ipd_emb);
    k_w16   <<<H_ * H_ / 256, 256>>>(h2h_w);
    k_rnn   <<<128, 256, SMEM_BYTES>>>(x);
    k_fc2   <<<B_ / 16, 256>>>(fc2_w, fc2_b, out);
}

// round 13
// speedup vs baseline: 1.1280x; 1.0868x over previous
#include <cuda_runtime.h>
#include <cuda_fp16.h>
#include <cstdint>

#define B_    1024
#define T_    128
#define H_    512
#define RNNIN 128
#define LENV  1500
#define IPDV  256
#define EB    64
#define LAB   100

#define MB   32
#define LDA  132
#define SMEM_BYTES (32768 + MB*LDA*4)   // sH(4x8KB swizzled) + sAcc

__device__ float  g_Wc[H_ * RNNIN];
__device__ float  g_c[H_];
__device__ float  g_Alen[LENV * H_];
__device__ float  g_Aipd[IPDV * H_];
__device__ __half g_W16[H_ * H_];                          // h2h_w [n][k] fp16
__device__ __align__(256) __half g_h16[2][4][1024][128];   // [buf][kchunk][row][128h] swizzled
__device__ float  g_hlast[B_ * H_];

// ---------------- kernel A: Wc = x2h_w @ fc1_w ; folded bias ----------------
__global__ void k_prep(const float* __restrict__ fc1_w, const float* __restrict__ fc1_b,
                       const float* __restrict__ x2h_w, const float* __restrict__ x2h_b,
                       const float* __restrict__ h2h_b) {
    __shared__ float s[RNNIN];
    int n = blockIdx.x, f = threadIdx.x;
    s[f] = x2h_w[n * RNNIN + f];
    __syncthreads();
    float acc = 0.f;
#pragma unroll 4
    for (int j = 0; j < RNNIN; ++j) acc += s[j] * fc1_w[j * 128 + f];
    g_Wc[n * RNNIN + f] = acc;
    if (f == 0) {
        float cb = x2h_b[n] + h2h_b[n];
        for (int j = 0; j < RNNIN; ++j) cb += s[j] * fc1_b[j];
        g_c[n] = cb;
    }
}

// ---------------- kernel B: fused embedding tables ----------------
#define RPB 16
__global__ void k_tables(const float* __restrict__ len_emb, const float* __restrict__ ipd_emb) {
    __shared__ float se[RPB][EB];
    int bid = blockIdx.x;
    const int lenBlocks = (LENV + RPB - 1) / RPB;
    bool isLen = bid < lenBlocks;
    int rbase, nrows, koff;
    const float* emb;
    float* dst;
    if (isLen) { rbase = bid * RPB;               nrows = LENV; koff = 0;  emb = len_emb; dst = g_Alen; }
    else       { rbase = (bid - lenBlocks) * RPB; nrows = IPDV; koff = EB; emb = ipd_emb; dst = g_Aipd; }
    for (int i = threadIdx.x; i < RPB * EB; i += blockDim.x) {
        int r = i / EB, k = i % EB;
        se[r][k] = (rbase + r < nrows) ? emb[(size_t)(rbase + r) * EB + k] : 0.f;
    }
    __syncthreads();
    int f = threadIdx.x;
    for (int q = 0; q < 4; ++q) {
        int n = q * 128 + f;
        float acc[RPB];
        float c0 = isLen ? g_c[n] : 0.f;
#pragma unroll
        for (int r = 0; r < RPB; ++r) acc[r] = c0;
        const float* wr = g_Wc + n * RNNIN + koff;
        for (int k = 0; k < EB; ++k) {
            float w = wr[k];
#pragma unroll
            for (int r = 0; r < RPB; ++r) acc[r] += w * se[r][k];
        }
        for (int r = 0; r < RPB; ++r)
            if (rbase + r < nrows) dst[(size_t)(rbase + r) * H_ + n] = acc[r];
    }
}

// ---------------- kernel C: h2h_w -> fp16 ----------------
__global__ void k_w16(const float* __restrict__ h2h_w) {
    int i = blockIdx.x * 256 + threadIdx.x;
    g_W16[i] = __float2half(h2h_w[i]);
}

// ---------------- helpers ----------------
__device__ __forceinline__ unsigned smem_u32(const void* p) {
    unsigned a;
    asm("{ .reg .u64 t; cvta.to.shared.u64 t, %1; cvt.u32.u64 %0, t; }" : "=r"(a) : "l"(p));
    return a;
}
__device__ __forceinline__ uint32_t h2_u32(__half2 h) {
    union { __half2 h; uint32_t u; } cv;
    cv.h = h;
    return cv.u;
}
// fast tanh: 1 - 2/(exp(2x)+1) via MUFU.EX2 + MUFU.RCP; |abs err| <~ 1e-6,
// saturates correctly to +-1 for large |x|.
__device__ __forceinline__ float ftanh(float x) {
    float e, r;
    asm("ex2.approx.f32 %0, %1;" : "=f"(e) : "f"(x * 2.885390081777927f));
    asm("rcp.approx.f32 %0, %1;" : "=f"(r) : "f"(e + 1.0f));
    return __fmaf_rn(-2.0f, r, 1.0f);
}
#define MBAR_INIT(a, c) asm volatile("mbarrier.init.shared.b64 [%0], %1;" :: "r"(a), "r"(c) : "memory")
#define MBAR_TX(a, b)   asm volatile("mbarrier.arrive.expect_tx.shared.b64 _, [%0], %1;" :: "r"(a), "r"(b) : "memory")
#define MBAR_WAIT(a, p) do { \
    asm volatile("{\n\t.reg .pred P;\n\tWL_%=:\n\t" \
        "mbarrier.try_wait.parity.acquire.cta.shared::cta.b64 P, [%0], %1, 0x989680;\n\t" \
        "@P bra.uni WD_%=;\n\tbra.uni WL_%=;\n\tWD_%=:\n\t}" :: "r"(a), "r"(p) : "memory"); } while (0)
#define BULK_G2S(d, s, n, m) \
    asm volatile("cp.async.bulk.shared::cta.global.mbarrier::complete_tx::bytes [%0], [%1], %2, [%3];" \
        :: "r"(d), "l"(s), "r"(n), "r"(m) : "memory")

// ---------------- kernel D: recurrence ----------------
__global__ void __cluster_dims__(4, 1, 1) __launch_bounds__(256, 1)
k_rnn(const int* __restrict__ x) {
    extern __shared__ __half smem[];
    __shared__ __align__(8) unsigned long long mbar[4];
    __half* sH   = smem;                        // 4 chunks x [32 rows][128h] swizzled = 32KB
    float*  sAcc = (float*)(smem + 16384);      // [MB][LDA]
    const unsigned sHu = smem_u32(sH);
    const unsigned mbu = smem_u32(mbar);

    const int rank = blockIdx.x & 3, cid = blockIdx.x >> 2;
    const int batch0 = cid * MB, n0 = rank * 128, tid = threadIdx.x;
    const int w = tid >> 5, lane = tid & 31;
    const int gid = lane >> 2, tig = lane & 3;
    const int nw = n0 + w * 16;
    const int r15 = lane & 15, g15 = lane >> 4;

    if (tid == 0) {
#pragma unroll
        for (int c = 0; c < 4; ++c) MBAR_INIT(mbu + 8 * c, 1);
    }
    __syncthreads();

    // persistent B (=W) fragments: 32 kk x 2 n8-tiles x 2 regs
    uint32_t bw[32][2][2];
#pragma unroll
    for (int kk = 0; kk < 32; ++kk)
#pragma unroll
        for (int j = 0; j < 2; ++j) {
            const __half* wp = g_W16 + (size_t)(nw + j * 8 + gid) * H_ + kk * 16 + tig * 2;
            bw[kk][j][0] = *(const uint32_t*)wp;
            bw[kk][j][1] = *(const uint32_t*)(wp + 8);
        }

    // epilogue mapping: row er, 16 cols at nl
    const int er = tid >> 3, nl = (tid & 7) * 16;
    const int eb = batch0 + er;
    const int* xp = x + (size_t)eb * T_ * 2;
    const unsigned sswz = (unsigned)(er & 15);
    const int u0 = (tid & 7) * 2;
    // h store base for this thread's row (chunk = rank)
    char* const hrow0 = (char*)g_h16 + ((size_t)rank * 1024 + eb) * 256;
    float4* const dlast = (float4*)(g_hlast + (size_t)eb * H_ + n0 + nl);

    // ---------------- t = 0 (epilogue-only, h0 = 0) ----------------
    float4 tl[4], ti[4];
    {
        int i0 = xp[0], i1 = xp[1];
        const float4* pa = (const float4*)(g_Alen + (size_t)i0 * H_ + n0 + nl);
        const float4* pb = (const float4*)(g_Aipd + (size_t)i1 * H_ + n0 + nl);
#pragma unroll
        for (int j = 0; j < 4; ++j) { tl[j] = pa[j]; ti[j] = pb[j]; }
        uint32_t hv[8];
#pragma unroll
        for (int j = 0; j < 4; ++j) {
            float4 o;
            o.x = ftanh(tl[j].x + ti[j].x);
            o.y = ftanh(tl[j].y + ti[j].y);
            o.z = ftanh(tl[j].z + ti[j].z);
            o.w = ftanh(tl[j].w + ti[j].w);
            hv[j * 2]     = h2_u32(__floats2half2_rn(o.x, o.y));
            hv[j * 2 + 1] = h2_u32(__floats2half2_rn(o.z, o.w));
        }
        *(uint4*)(hrow0 + (((unsigned)u0 ^ sswz) << 4))       = ((uint4*)hv)[0];
        *(uint4*)(hrow0 + (((unsigned)(u0 + 1) ^ sswz) << 4)) = ((uint4*)hv)[1];
        // prefetch tables for t=1 (in flight during barrier)
        int j0 = xp[2], j1 = xp[3];
        const float4* qa = (const float4*)(g_Alen + (size_t)j0 * H_ + n0 + nl);
        const float4* qb = (const float4*)(g_Aipd + (size_t)j1 * H_ + n0 + nl);
#pragma unroll
        for (int j = 0; j < 4; ++j) { tl[j] = qa[j]; ti[j] = qb[j]; }
        asm volatile("fence.proxy.async;" ::: "memory");
        asm volatile("barrier.cluster.arrive.aligned;" ::: "memory");
        asm volatile("barrier.cluster.wait.aligned;"   ::: "memory");
    }

    // ---------------- t = 1 .. 127 ----------------
    for (int t = 1; t < T_; ++t) {
        const int rb = (t - 1) & 1, p = (t - 1) & 1;

        if (tid == 0) {
#pragma unroll
            for (int c = 0; c < 4; ++c) {
                MBAR_TX(mbu + 8 * c, 8192);
                BULK_G2S(sHu + c * 8192,
                         (const char*)g_h16 + (((size_t)rb * 4 + c) * 1024 + batch0) * 256,
                         8192, mbu + 8 * c);
            }
        }

        // GEMM [32 x 512] @ W^T -> warp tile [32 m x 16 n], chunk-pipelined
        float ac[2][2][4];
#pragma unroll
        for (int mt = 0; mt < 2; ++mt)
#pragma unroll
            for (int j = 0; j < 2; ++j)
#pragma unroll
                for (int q = 0; q < 4; ++q) ac[mt][j][q] = 0.f;

#pragma unroll
        for (int c = 0; c < 4; ++c) {
            MBAR_WAIT(mbu + 8 * c, p);
#pragma unroll
            for (int kc = 0; kc < 8; ++kc) {
#pragma unroll
                for (int mt = 0; mt < 2; ++mt) {
                    unsigned unit = ((unsigned)(2 * kc + g15) ^ (unsigned)r15) << 4;
                    unsigned ad = sHu + c * 8192 + (mt * 16 + r15) * 256 + unit;
                    uint32_t a0, a1, a2, a3;
                    asm volatile("ldmatrix.sync.aligned.m8n8.x4.shared.b16 {%0,%1,%2,%3}, [%4];"
                                 : "=r"(a0), "=r"(a1), "=r"(a2), "=r"(a3) : "r"(ad));
                    const int kk = c * 8 + kc;
#pragma unroll
                    for (int j = 0; j < 2; ++j)
                        asm volatile(
                            "mma.sync.aligned.m16n8k16.row.col.f32.f16.f16.f32 "
                            "{%0,%1,%2,%3},{%4,%5,%6,%7},{%8,%9},{%0,%1,%2,%3};"
                            : "+f"(ac[mt][j][0]), "+f"(ac[mt][j][1]),
                              "+f"(ac[mt][j][2]), "+f"(ac[mt][j][3])
                            : "r"(a0), "r"(a1), "r"(a2), "r"(a3),
                              "r"(bw[kk][j][0]), "r"(bw[kk][j][1]));
                }
            }
        }

        // stash acc to sAcc for row-coherent epilogue
#pragma unroll
        for (int mt = 0; mt < 2; ++mt)
#pragma unroll
            for (int j = 0; j < 2; ++j) {
                int n = w * 16 + j * 8 + tig * 2;
                float* p0 = sAcc + (mt * 16 + gid) * LDA + n;
                float* p1 = sAcc + (mt * 16 + gid + 8) * LDA + n;
                p0[0] = ac[mt][j][0]; p0[1] = ac[mt][j][1];
                p1[0] = ac[mt][j][2]; p1[1] = ac[mt][j][3];
            }
        __syncthreads();

        // epilogue: tanh(acc + A_len + A_ipd)
        const float4* pq = (const float4*)(sAcc + er * LDA + nl);
        uint32_t hv[8];
        float4 fres[4];
#pragma unroll
        for (int j = 0; j < 4; ++j) {
            float4 qa = pq[j];
            float4 o;
            o.x = ftanh(qa.x + tl[j].x + ti[j].x);
            o.y = ftanh(qa.y + tl[j].y + ti[j].y);
            o.z = ftanh(qa.z + tl[j].z + ti[j].z);
            o.w = ftanh(qa.w + tl[j].w + ti[j].w);
            fres[j] = o;
            hv[j * 2]     = h2_u32(__floats2half2_rn(o.x, o.y));
            hv[j * 2 + 1] = h2_u32(__floats2half2_rn(o.z, o.w));
        }
        if (t < T_ - 1) {
            char* hrow = hrow0 + (size_t)(t & 1) * (4u * 1024u * 256u);
            *(uint4*)(hrow + (((unsigned)u0 ^ sswz) << 4))       = ((uint4*)hv)[0];
            *(uint4*)(hrow + (((unsigned)(u0 + 1) ^ sswz) << 4)) = ((uint4*)hv)[1];
            // prefetch tables for t+1 while barrier drains
            int j0 = xp[2 * (t + 1)], j1 = xp[2 * (t + 1) + 1];
            const float4* qa2 = (const float4*)(g_Alen + (size_t)j0 * H_ + n0 + nl);
            const float4* qb2 = (const float4*)(g_Aipd + (size_t)j1 * H_ + n0 + nl);
#pragma unroll
            for (int j = 0; j < 4; ++j) { tl[j] = qa2[j]; ti[j] = qb2[j]; }
            asm volatile("fence.proxy.async;" ::: "memory");
            asm volatile("barrier.cluster.arrive.aligned;" ::: "memory");
            asm volatile("barrier.cluster.wait.aligned;"   ::: "memory");
        } else {
#pragma unroll
            for (int j = 0; j < 4; ++j) dlast[j] = fres[j];
        }
    }
}

// ---------------- kernel E: fc2 ----------------
__global__ void k_fc2(const float* __restrict__ fc2_w, const float* __restrict__ fc2_b,
                      float* __restrict__ out) {
    __shared__ float sh[16][H_];
    int batch0 = blockIdx.x * 16;
    for (int i = threadIdx.x; i < 16 * H_; i += 256) {
        int r = i >> 9, k = i & (H_ - 1);
        sh[r][k] = g_hlast[(size_t)(batch0 + r) * H_ + k];
    }
    __syncthreads();
    int tid = threadIdx.x;
    if (tid < 200) {
        int l = tid % 100, bh = tid / 100;
        float acc[8];
        float bias = fc2_b[l];
#pragma unroll
        for (int i = 0; i < 8; ++i) acc[i] = bias;
        const float4* wr = (const float4*)(fc2_w + (size_t)l * H_);
        for (int k4 = 0; k4 < H_ / 4; ++k4) {
            float4 wv = wr[k4];
#pragma unroll
            for (int i = 0; i < 8; ++i) {
                float4 h = *(const float4*)(&sh[bh * 8 + i][k4 * 4]);
                acc[i] += wv.x * h.x + wv.y * h.y + wv.z * h.z + wv.w * h.w;
            }
        }
        for (int i = 0; i < 8; ++i)
            out[(size_t)(batch0 + bh * 8 + i) * LAB + l] = acc[i];
    }
}

// ---------------- launch ----------------
extern "C" void kernel_launch(void* const* d_in, const int* in_sizes, int n_in,
                              void* d_out, int out_size) {
    const int* x         = (const int*)d_in[0];
    const float* len_emb = (const float*)d_in[1];
    const float* ipd_emb = (const float*)d_in[2];
    const float* fc1_w   = (const float*)d_in[3];
    const float* fc1_b   = (const float*)d_in[4];
    const float* x2h_w   = (const float*)d_in[5];
    const float* x2h_b   = (const float*)d_in[6];
    const float* h2h_w   = (const float*)d_in[7];
    const float* h2h_b   = (const float*)d_in[8];
    const float* fc2_w   = (const float*)d_in[9];
    const float* fc2_b   = (const float*)d_in[10];
    float* out = (float*)d_out;

    cudaFuncSetAttribute(k_rnn, cudaFuncAttributeMaxDynamicSharedMemorySize, SMEM_BYTES);

    k_prep  <<<512, 128>>>(fc1_w, fc1_b, x2h_w, x2h_b, h2h_b);
    k_tables<<<(LENV + RPB - 1) / RPB + IPDV / RPB, 128>>>(len_emb, ipd_emb);
    k_w16   <<<H_ * H_ / 256, 256>>>(h2h_w);
    k_rnn   <<<128, 256, SMEM_BYTES>>>(x);
    k_fc2   <<<B_ / 16, 256>>>(fc2_w, fc2_b, out);
}

// round 14
// speedup vs baseline: 1.1640x; 1.0319x over previous
#include <cuda_runtime.h>
#include <cuda_fp16.h>
#include <cstdint>

#define B_    1024
#define T_    128
#define H_    512
#define RNNIN 128
#define LENV  1500
#define IPDV  256
#define EB    64
#define LAB   100

#define LDA  68
#define SMEM_BYTES (32768 + 32*LDA*4)   // sH(4x8KB swizzled) + sAcc[32][68]

__device__ float  g_Wc[H_ * RNNIN];
__device__ float  g_c[H_];
__device__ float  g_Alen[LENV * H_];
__device__ float  g_Aipd[IPDV * H_];
__device__ __half g_W16[H_ * H_];                          // h2h_w [n][k] fp16
__device__ __align__(256) __half g_h16[2][4][1024][128];   // [buf][kchunk][row][128h] swizzled
__device__ float  g_hlast[B_ * H_];

// ---------------- kernel A: Wc = x2h_w @ fc1_w ; folded bias ----------------
__global__ void k_prep(const float* __restrict__ fc1_w, const float* __restrict__ fc1_b,
                       const float* __restrict__ x2h_w, const float* __restrict__ x2h_b,
                       const float* __restrict__ h2h_b) {
    __shared__ float s[RNNIN];
    int n = blockIdx.x, f = threadIdx.x;
    s[f] = x2h_w[n * RNNIN + f];
    __syncthreads();
    float acc = 0.f;
#pragma unroll 4
    for (int j = 0; j < RNNIN; ++j) acc += s[j] * fc1_w[j * 128 + f];
    g_Wc[n * RNNIN + f] = acc;
    if (f == 0) {
        float cb = x2h_b[n] + h2h_b[n];
        for (int j = 0; j < RNNIN; ++j) cb += s[j] * fc1_b[j];
        g_c[n] = cb;
    }
}

// ---------------- kernel B: fused embedding tables ----------------
#define RPB 16
__global__ void k_tables(const float* __restrict__ len_emb, const float* __restrict__ ipd_emb) {
    __shared__ float se[RPB][EB];
    int bid = blockIdx.x;
    const int lenBlocks = (LENV + RPB - 1) / RPB;
    bool isLen = bid < lenBlocks;
    int rbase, nrows, koff;
    const float* emb;
    float* dst;
    if (isLen) { rbase = bid * RPB;               nrows = LENV; koff = 0;  emb = len_emb; dst = g_Alen; }
    else       { rbase = (bid - lenBlocks) * RPB; nrows = IPDV; koff = EB; emb = ipd_emb; dst = g_Aipd; }
    for (int i = threadIdx.x; i < RPB * EB; i += blockDim.x) {
        int r = i / EB, k = i % EB;
        se[r][k] = (rbase + r < nrows) ? emb[(size_t)(rbase + r) * EB + k] : 0.f;
    }
    __syncthreads();
    int f = threadIdx.x;
    for (int q = 0; q < 4; ++q) {
        int n = q * 128 + f;
        float acc[RPB];
        float c0 = isLen ? g_c[n] : 0.f;
#pragma unroll
        for (int r = 0; r < RPB; ++r) acc[r] = c0;
        const float* wr = g_Wc + n * RNNIN + koff;
        for (int k = 0; k < EB; ++k) {
            float w = wr[k];
#pragma unroll
            for (int r = 0; r < RPB; ++r) acc[r] += w * se[r][k];
        }
        for (int r = 0; r < RPB; ++r)
            if (rbase + r < nrows) dst[(size_t)(rbase + r) * H_ + n] = acc[r];
    }
}

// ---------------- kernel C: h2h_w -> fp16 ----------------
__global__ void k_w16(const float* __restrict__ h2h_w) {
    int i = blockIdx.x * 256 + threadIdx.x;
    g_W16[i] = __float2half(h2h_w[i]);
}

// ---------------- helpers ----------------
__device__ __forceinline__ unsigned smem_u32(const void* p) {
    unsigned a;
    asm("{ .reg .u64 t; cvta.to.shared.u64 t, %1; cvt.u32.u64 %0, t; }" : "=r"(a) : "l"(p));
    return a;
}
__device__ __forceinline__ uint32_t h2_u32(__half2 h) {
    union { __half2 h; uint32_t u; } cv;
    cv.h = h;
    return cv.u;
}
// fast tanh: 1 - 2/(exp(2x)+1) via MUFU.EX2 + MUFU.RCP
__device__ __forceinline__ float ftanh(float x) {
    float e, r;
    asm("ex2.approx.f32 %0, %1;" : "=f"(e) : "f"(x * 2.885390081777927f));
    asm("rcp.approx.f32 %0, %1;" : "=f"(r) : "f"(e + 1.0f));
    return __fmaf_rn(-2.0f, r, 1.0f);
}
#define MBAR_INIT(a, c) asm volatile("mbarrier.init.shared.b64 [%0], %1;" :: "r"(a), "r"(c) : "memory")
#define MBAR_TX(a, b)   asm volatile("mbarrier.arrive.expect_tx.shared.b64 _, [%0], %1;" :: "r"(a), "r"(b) : "memory")
#define MBAR_WAIT(a, p) do { \
    asm volatile("{\n\t.reg .pred P;\n\tWL_%=:\n\t" \
        "mbarrier.try_wait.parity.acquire.cta.shared::cta.b64 P, [%0], %1, 0x989680;\n\t" \
        "@P bra.uni WD_%=;\n\tbra.uni WL_%=;\n\tWD_%=:\n\t}" :: "r"(a), "r"(p) : "memory"); } while (0)
#define BULK_G2S(d, s, n, m) \
    asm volatile("cp.async.bulk.shared::cta.global.mbarrier::complete_tx::bytes [%0], [%1], %2, [%3];" \
        :: "r"(d), "l"(s), "r"(n), "r"(m) : "memory")

// ---------------- kernel D: recurrence (8-CTA cluster, 128-thread CTAs) ----------------
__global__ void __cluster_dims__(8, 1, 1) __launch_bounds__(128, 2)
k_rnn(const int* __restrict__ x) {
    extern __shared__ __half smem[];
    __shared__ __align__(8) unsigned long long mbar[4];
    __half* sH   = smem;                        // 4 chunks x [32 rows][128h] swizzled = 32KB
    float*  sAcc = (float*)(smem + 16384);      // [32][LDA]
    const unsigned sHu = smem_u32(sH);
    const unsigned mbu = smem_u32(mbar);

    const int rank = blockIdx.x & 7, cid = blockIdx.x >> 3;
    const int batch0 = cid * 32, n0 = rank * 64, tid = threadIdx.x;
    const int w = tid >> 5, lane = tid & 31;
    const int gid = lane >> 2, tig = lane & 3;
    const int nw = n0 + w * 16;
    const int r15 = lane & 15, g15 = lane >> 4;

    if (tid == 0) {
#pragma unroll
        for (int c = 0; c < 4; ++c) MBAR_INIT(mbu + 8 * c, 1);
    }
    __syncthreads();

    // persistent B (=W) fragments: 32 kk x 2 n8-tiles x 2 regs
    uint32_t bw[32][2][2];
#pragma unroll
    for (int kk = 0; kk < 32; ++kk)
#pragma unroll
        for (int j = 0; j < 2; ++j) {
            const __half* wp = g_W16 + (size_t)(nw + j * 8 + gid) * H_ + kk * 16 + tig * 2;
            bw[kk][j][0] = *(const uint32_t*)wp;
            bw[kk][j][1] = *(const uint32_t*)(wp + 8);
        }

    // epilogue mapping: 128 threads = 32 rows x 4 col-groups of 16
    const int er = tid >> 2, nl = (tid & 3) * 16;
    const int eb = batch0 + er;
    const int* xp = x + (size_t)eb * T_ * 2;
    const unsigned sswz = (unsigned)(er & 15);
    const int u0 = (rank & 1) * 8 + (tid & 3) * 2;      // unit within 256B k-chunk row
    // h store base: this CTA's cols live in k-chunk rank>>1
    char* const hrow0 = (char*)g_h16 + (((size_t)(rank >> 1)) * 1024 + eb) * 256;
    float4* const dlast = (float4*)(g_hlast + (size_t)eb * H_ + n0 + nl);

    // ---------------- t = 0 (epilogue-only, h0 = 0) ----------------
    float4 tl[4], ti[4];
    {
        int i0 = xp[0], i1 = xp[1];
        const float4* pa = (const float4*)(g_Alen + (size_t)i0 * H_ + n0 + nl);
        const float4* pb = (const float4*)(g_Aipd + (size_t)i1 * H_ + n0 + nl);
#pragma unroll
        for (int j = 0; j < 4; ++j) { tl[j] = pa[j]; ti[j] = pb[j]; }
        uint32_t hv[8];
#pragma unroll
        for (int j = 0; j < 4; ++j) {
            float4 o;
            o.x = ftanh(tl[j].x + ti[j].x);
            o.y = ftanh(tl[j].y + ti[j].y);
            o.z = ftanh(tl[j].z + ti[j].z);
            o.w = ftanh(tl[j].w + ti[j].w);
            hv[j * 2]     = h2_u32(__floats2half2_rn(o.x, o.y));
            hv[j * 2 + 1] = h2_u32(__floats2half2_rn(o.z, o.w));
        }
        *(uint4*)(hrow0 + (((unsigned)u0 ^ sswz) << 4))       = ((uint4*)hv)[0];
        *(uint4*)(hrow0 + (((unsigned)(u0 + 1) ^ sswz) << 4)) = ((uint4*)hv)[1];
        // prefetch tables for t=1 (in flight during barrier)
        int j0 = xp[2], j1 = xp[3];
        const float4* qa = (const float4*)(g_Alen + (size_t)j0 * H_ + n0 + nl);
        const float4* qb = (const float4*)(g_Aipd + (size_t)j1 * H_ + n0 + nl);
#pragma unroll
        for (int j = 0; j < 4; ++j) { tl[j] = qa[j]; ti[j] = qb[j]; }
        asm volatile("fence.proxy.async;" ::: "memory");
        asm volatile("barrier.cluster.arrive.aligned;" ::: "memory");
        asm volatile("barrier.cluster.wait.aligned;"   ::: "memory");
    }

    // ---------------- t = 1 .. 127 ----------------
    for (int t = 1; t < T_; ++t) {
        const int rb = (t - 1) & 1, p = (t - 1) & 1;

        if (tid == 0) {
#pragma unroll
            for (int c = 0; c < 4; ++c) {
                MBAR_TX(mbu + 8 * c, 8192);
                BULK_G2S(sHu + c * 8192,
                         (const char*)g_h16 + (((size_t)rb * 4 + c) * 1024 + batch0) * 256,
                         8192, mbu + 8 * c);
            }
        }

        // GEMM [32 x 512] @ W^T -> warp tile [32 m x 16 n], chunk-pipelined
        float ac[2][2][4];
#pragma unroll
        for (int mt = 0; mt < 2; ++mt)
#pragma unroll
            for (int j = 0; j < 2; ++j)
#pragma unroll
                for (int q = 0; q < 4; ++q) ac[mt][j][q] = 0.f;

#pragma unroll
        for (int c = 0; c < 4; ++c) {
            MBAR_WAIT(mbu + 8 * c, p);
#pragma unroll
            for (int kc = 0; kc < 8; ++kc) {
#pragma unroll
                for (int mt = 0; mt < 2; ++mt) {
                    unsigned unit = ((unsigned)(2 * kc + g15) ^ (unsigned)r15) << 4;
                    unsigned ad = sHu + c * 8192 + (mt * 16 + r15) * 256 + unit;
                    uint32_t a0, a1, a2, a3;
                    asm volatile("ldmatrix.sync.aligned.m8n8.x4.shared.b16 {%0,%1,%2,%3}, [%4];"
                                 : "=r"(a0), "=r"(a1), "=r"(a2), "=r"(a3) : "r"(ad));
                    const int kk = c * 8 + kc;
#pragma unroll
                    for (int j = 0; j < 2; ++j)
                        asm volatile(
                            "mma.sync.aligned.m16n8k16.row.col.f32.f16.f16.f32 "
                            "{%0,%1,%2,%3},{%4,%5,%6,%7},{%8,%9},{%0,%1,%2,%3};"
                            : "+f"(ac[mt][j][0]), "+f"(ac[mt][j][1]),
                              "+f"(ac[mt][j][2]), "+f"(ac[mt][j][3])
                            : "r"(a0), "r"(a1), "r"(a2), "r"(a3),
                              "r"(bw[kk][j][0]), "r"(bw[kk][j][1]));
                }
            }
        }

        // stash acc to sAcc for row-coherent epilogue
#pragma unroll
        for (int mt = 0; mt < 2; ++mt)
#pragma unroll
            for (int j = 0; j < 2; ++j) {
                int n = w * 16 + j * 8 + tig * 2;
                float* p0 = sAcc + (mt * 16 + gid) * LDA + n;
                float* p1 = sAcc + (mt * 16 + gid + 8) * LDA + n;
                p0[0] = ac[mt][j][0]; p0[1] = ac[mt][j][1];
                p1[0] = ac[mt][j][2]; p1[1] = ac[mt][j][3];
            }
        __syncthreads();

        // epilogue: tanh(acc + A_len + A_ipd)
        const float4* pq = (const float4*)(sAcc + er * LDA + nl);
        uint32_t hv[8];
        float4 fres[4];
#pragma unroll
        for (int j = 0; j < 4; ++j) {
            float4 qa = pq[j];
            float4 o;
            o.x = ftanh(qa.x + tl[j].x + ti[j].x);
            o.y = ftanh(qa.y + tl[j].y + ti[j].y);
            o.z = ftanh(qa.z + tl[j].z + ti[j].z);
            o.w = ftanh(qa.w + tl[j].w + ti[j].w);
            fres[j] = o;
            hv[j * 2]     = h2_u32(__floats2half2_rn(o.x, o.y));
            hv[j * 2 + 1] = h2_u32(__floats2half2_rn(o.z, o.w));
        }
        if (t < T_ - 1) {
            char* hrow = hrow0 + (size_t)(t & 1) * (4u * 1024u * 256u);
            *(uint4*)(hrow + (((unsigned)u0 ^ sswz) << 4))       = ((uint4*)hv)[0];
            *(uint4*)(hrow + (((unsigned)(u0 + 1) ^ sswz) << 4)) = ((uint4*)hv)[1];
            // prefetch tables for t+1 while barrier drains
            int j0 = xp[2 * (t + 1)], j1 = xp[2 * (t + 1) + 1];
            const float4* qa2 = (const float4*)(g_Alen + (size_t)j0 * H_ + n0 + nl);
            const float4* qb2 = (const float4*)(g_Aipd + (size_t)j1 * H_ + n0 + nl);
#pragma unroll
            for (int j = 0; j < 4; ++j) { tl[j] = qa2[j]; ti[j] = qb2[j]; }
            asm volatile("fence.proxy.async;" ::: "memory");
            asm volatile("barrier.cluster.arrive.aligned;" ::: "memory");
            asm volatile("barrier.cluster.wait.aligned;"   ::: "memory");
        } else {
#pragma unroll
            for (int j = 0; j < 4; ++j) dlast[j] = fres[j];
        }
    }
}

// ---------------- kernel E: fc2 ----------------
__global__ void k_fc2(const float* __restrict__ fc2_w, const float* __restrict__ fc2_b,
                      float* __restrict__ out) {
    __shared__ float sh[16][H_];
    int batch0 = blockIdx.x * 16;
    for (int i = threadIdx.x; i < 16 * H_; i += 256) {
        int r = i >> 9, k = i & (H_ - 1);
        sh[r][k] = g_hlast[(size_t)(batch0 + r) * H_ + k];
    }
    __syncthreads();
    int tid = threadIdx.x;
    if (tid < 200) {
        int l = tid % 100, bh = tid / 100;
        float acc[8];
        float bias = fc2_b[l];
#pragma unroll
        for (int i = 0; i < 8; ++i) acc[i] = bias;
        const float4* wr = (const float4*)(fc2_w + (size_t)l * H_);
        for (int k4 = 0; k4 < H_ / 4; ++k4) {
            float4 wv = wr[k4];
#pragma unroll
            for (int i = 0; i < 8; ++i) {
                float4 h = *(const float4*)(&sh[bh * 8 + i][k4 * 4]);
                acc[i] += wv.x * h.x + wv.y * h.y + wv.z * h.z + wv.w * h.w;
            }
        }
        for (int i = 0; i < 8; ++i)
            out[(size_t)(batch0 + bh * 8 + i) * LAB + l] = acc[i];
    }
}

// ---------------- launch ----------------
extern "C" void kernel_launch(void* const* d_in, const int* in_sizes, int n_in,
                              void* d_out, int out_size) {
    const int* x         = (const int*)d_in[0];
    const float* len_emb = (const float*)d_in[1];
    const float* ipd_emb = (const float*)d_in[2];
    const float* fc1_w   = (const float*)d_in[3];
    const float* fc1_b   = (const float*)d_in[4];
    const float* x2h_w   = (const float*)d_in[5];
    const float* x2h_b   = (const float*)d_in[6];
    const float* h2h_w   = (const float*)d_in[7];
    const float* h2h_b   = (const float*)d_in[8];
    const float* fc2_w   = (const float*)d_in[9];
    const float* fc2_b   = (const float*)d_in[10];
    float* out = (float*)d_out;

    cudaFuncSetAttribute(k_rnn, cudaFuncAttributeMaxDynamicSharedMemorySize, SMEM_BYTES);

    k_prep  <<<512, 128>>>(fc1_w, fc1_b, x2h_w, x2h_b, h2h_b);
    k_tables<<<(LENV + RPB - 1) / RPB + IPDV / RPB, 128>>>(len_emb, ipd_emb);
    k_w16   <<<H_ * H_ / 256, 256>>>(h2h_w);
    k_rnn   <<<256, 128, SMEM_BYTES>>>(x);
    k_fc2   <<<B_ / 16, 256>>>(fc2_w, fc2_b, out);
}